// round 8
// baseline (speedup 1.0000x reference)
#include <cuda_runtime.h>
#include <cuda_fp16.h>

#define EPS 1e-4f
#define NDIM 512
#define H2S 131072            // half2 per sample (512*256)
#define PAD 261               // tile row stride in half2 (conflict-free transpose)

__device__ __half2 g_H [128 * (size_t)H2S];   // row-major fp16 copy (64 MB)
__device__ __half2 g_HT[128 * (size_t)H2S];   // transposed fp16 copy (64 MB)

__device__ __forceinline__ float4 z4f() { return make_float4(0.f, 0.f, 0.f, 0.f); }
__device__ __forceinline__ float2 h2f(unsigned u) {
    __half2 h = *reinterpret_cast<__half2*>(&u);
    return __half22float2(h);
}
__device__ __forceinline__ void acc8(float* a, uint4 u, float wv) {
    float2 f0 = h2f(u.x), f1 = h2f(u.y), f2 = h2f(u.z), f3 = h2f(u.w);
    a[0] = fmaf(wv, f0.x, a[0]); a[1] = fmaf(wv, f0.y, a[1]);
    a[2] = fmaf(wv, f1.x, a[2]); a[3] = fmaf(wv, f1.y, a[3]);
    a[4] = fmaf(wv, f2.x, a[4]); a[5] = fmaf(wv, f2.y, a[5]);
    a[6] = fmaf(wv, f3.x, a[6]); a[7] = fmaf(wv, f3.y, a[7]);
}

__global__ __launch_bounds__(1024, 1)
void sinkhorn_kernel(const float* __restrict__ s,
                     const int* __restrict__ nrows,
                     float* __restrict__ out) {
    extern __shared__ __align__(16) float smem[];   // 49792 B dynamic
    float* red = smem;                               // [0, 8192) floats (iter passes use 16*512)
    __half2* tile = (__half2*)(smem + 4096);         // 32*PAD half2 (pass0 only)
    __shared__ __align__(16) float r_sh[NDIM];
    __shared__ __align__(16) float c_sh[NDIM];
    __shared__ float ssum[32];

    const int b = blockIdx.x, tid = threadIdx.x;
    const int lane = tid & 31, wid = tid >> 5;
    const int n  = nrows[b];
    const int nt = (n + 31) & ~31;
    const float* __restrict__ S = s + (size_t)b * NDIM * NDIM;
    float* __restrict__ O = out + (size_t)b * NDIM * NDIM;
    __half2* __restrict__ H2  = g_H  + (size_t)b * H2S;
    __half2* __restrict__ HT2 = g_HT + (size_t)b * H2S;

    // ===== pass 0: col sums (r=1) + build H (row-major) and HT (transposed) ====
    const int j4    = (tid & 127) << 2;
    const int jhp   = j4 >> 1;
    const int slice = tid >> 7;            // 0..7
    const int jh2   = tid >> 2;            // 0..255 (transpose role: half2 column)
    const int kk    = tid & 3;             // 0..3  (transpose role: k-block)
    float4 ca = z4f();

    for (int i0 = 0; i0 < nt; i0 += 32) {
        #pragma unroll
        for (int m = 0; m < 4; ++m) {
            const int k = slice + m * 8;
            const int i = i0 + k;
            float4 v = z4f();
            if (i < n) v = __ldcs((const float4*)(S + (size_t)i * NDIM + j4));
            ca.x += v.x; ca.y += v.y; ca.z += v.z; ca.w += v.w;
            __half2 h0 = __floats2half2_rn(v.x, v.y);
            __half2 h1 = __floats2half2_rn(v.z, v.w);
            float2 p;
            p.x = __uint_as_float(*reinterpret_cast<unsigned*>(&h0));
            p.y = __uint_as_float(*reinterpret_cast<unsigned*>(&h1));
            *(float2*)(H2 + (size_t)i * 256 + jhp) = p;     // coalesced H write
            tile[k * PAD + jhp]     = h0;
            tile[k * PAD + jhp + 1] = h1;
        }
        __syncthreads();
        // transpose the 32x512 tile -> HT rows 2*jh2, 2*jh2+1, halves i0+8kk..+7
        unsigned u0 = *(const unsigned*)(tile + (kk * 8 + 0) * PAD + jh2);
        unsigned u1 = *(const unsigned*)(tile + (kk * 8 + 1) * PAD + jh2);
        unsigned u2 = *(const unsigned*)(tile + (kk * 8 + 2) * PAD + jh2);
        unsigned u3 = *(const unsigned*)(tile + (kk * 8 + 3) * PAD + jh2);
        unsigned u4 = *(const unsigned*)(tile + (kk * 8 + 4) * PAD + jh2);
        unsigned u5 = *(const unsigned*)(tile + (kk * 8 + 5) * PAD + jh2);
        unsigned u6 = *(const unsigned*)(tile + (kk * 8 + 6) * PAD + jh2);
        unsigned u7 = *(const unsigned*)(tile + (kk * 8 + 7) * PAD + jh2);
        uint4 A, B;
        A.x = __byte_perm(u0, u1, 0x5410); A.y = __byte_perm(u2, u3, 0x5410);
        A.z = __byte_perm(u4, u5, 0x5410); A.w = __byte_perm(u6, u7, 0x5410);
        B.x = __byte_perm(u0, u1, 0x7632); B.y = __byte_perm(u2, u3, 0x7632);
        B.z = __byte_perm(u4, u5, 0x7632); B.w = __byte_perm(u6, u7, 0x7632);
        *(uint4*)(HT2 + (size_t)(2 * jh2)     * 256 + (i0 >> 1) + 4 * kk) = A;
        *(uint4*)(HT2 + (size_t)(2 * jh2 + 1) * 256 + (i0 >> 1) + 4 * kk) = B;
        __syncthreads();
    }
    *(float4*)(red + slice * NDIM + j4) = ca;
    __syncthreads();

    float sum_c = 0.0f, sum_r = 0.0f;
    {
        float cv = 0.0f;
        if (tid < NDIM) {
            float cs = 0.0f;
            #pragma unroll
            for (int ss = 0; ss < 8; ++ss) cs += red[ss * NDIM + tid];
            if (tid < n) cv = 1.0f / (cs + EPS * (float)n);
            c_sh[tid] = cv;
        }
        float v = cv;
        #pragma unroll
        for (int o = 16; o; o >>= 1) v += __shfl_xor_sync(0xffffffffu, v, o);
        if (lane == 0) ssum[wid] = v;
        __syncthreads();
        #pragma unroll
        for (int k = 0; k < 32; ++k) sum_c += ssum[k];
    }

    // ===== 9 shuffle-free streaming passes (it=1 row, it=2 col, ... it=9 row) ===
    const int grp = (tid & 63) << 3;   // 8-half output group
    const int gh  = grp >> 1;          // half2 offset within a row
    const int sl  = tid >> 6;          // 0..15 slice over the summed dimension

    #pragma unroll 1
    for (int it = 1; it <= 9; ++it) {
        const bool rowstep = (it & 1);
        const __half2* __restrict__ M2 = rowstep ? HT2 : H2;
        const float*   __restrict__ w  = rowstep ? c_sh : r_sh;
        const float epsw = EPS * (rowstep ? sum_c : sum_r);

        float a[8] = {0.f, 0.f, 0.f, 0.f, 0.f, 0.f, 0.f, 0.f};
        int j = sl;
        for (; j + 48 < n; j += 64) {
            uint4 uA = *(const uint4*)(M2 + (size_t)(j)      * 256 + gh);
            uint4 uB = *(const uint4*)(M2 + (size_t)(j + 16) * 256 + gh);
            uint4 uC = *(const uint4*)(M2 + (size_t)(j + 32) * 256 + gh);
            uint4 uD = *(const uint4*)(M2 + (size_t)(j + 48) * 256 + gh);
            float wA = w[j], wB = w[j + 16], wC = w[j + 32], wD = w[j + 48];
            acc8(a, uA, wA); acc8(a, uB, wB); acc8(a, uC, wC); acc8(a, uD, wD);
        }
        for (; j < n; j += 16) {
            uint4 u = *(const uint4*)(M2 + (size_t)j * 256 + gh);
            acc8(a, u, w[j]);
        }
        *(float4*)(red + sl * NDIM + grp)     = make_float4(a[0], a[1], a[2], a[3]);
        *(float4*)(red + sl * NDIM + grp + 4) = make_float4(a[4], a[5], a[6], a[7]);
        __syncthreads();

        float val = 0.0f;
        if (tid < NDIM) {
            float t = 0.0f;
            #pragma unroll
            for (int ss = 0; ss < 16; ++ss) t += red[ss * NDIM + tid];
            if (tid < n) val = 1.0f / (t + epsw);
            (rowstep ? r_sh : c_sh)[tid] = val;
        }
        if (it < 9) {
            float v = val;
            #pragma unroll
            for (int o = 16; o; o >>= 1) v += __shfl_xor_sync(0xffffffffu, v, o);
            if (lane == 0) ssum[wid] = v;
            __syncthreads();
            float ts = 0.0f;
            #pragma unroll
            for (int k = 0; k < 32; ++k) ts += ssum[k];
            if (rowstep) sum_r = ts; else sum_c = ts;
        } else {
            __syncthreads();
        }
    }

    // ===== final fused write: out = (H+EPS)*r*c (zeros via r,c) ================
    const float4* __restrict__ c4s = (const float4*)c_sh;
    const uint4*  __restrict__ H4  = (const uint4*)H2;
    float4* __restrict__ O4 = (float4*)O;
    for (int d = tid; d < 32768; d += 1024) {
        const int i = d >> 6;
        const float ri = r_sh[i];
        float4 w0 = z4f(), w1 = z4f();
        if (ri != 0.0f) {
            uint4 u = H4[d];
            float4 cA = c4s[(d & 63) * 2], cB = c4s[(d & 63) * 2 + 1];
            float2 f0 = h2f(u.x), f1 = h2f(u.y), f2 = h2f(u.z), f3 = h2f(u.w);
            w0.x = (f0.x + EPS) * ri * cA.x; w0.y = (f0.y + EPS) * ri * cA.y;
            w0.z = (f1.x + EPS) * ri * cA.z; w0.w = (f1.y + EPS) * ri * cA.w;
            w1.x = (f2.x + EPS) * ri * cB.x; w1.y = (f2.y + EPS) * ri * cB.y;
            w1.z = (f3.x + EPS) * ri * cB.z; w1.w = (f3.y + EPS) * ri * cB.w;
        }
        __stcs(O4 + 2 * d, w0);
        __stcs(O4 + 2 * d + 1, w1);
    }
}

extern "C" void kernel_launch(void* const* d_in, const int* in_sizes, int n_in,
                              void* d_out, int out_size) {
    const float* s     = (const float*)d_in[0];
    const int*   nrows = (const int*)d_in[1];
    float*       out   = (float*)d_out;
    const int B = in_sizes[1];
    const int shbytes = (4096 + 32 * PAD) * 4;   // 49792 B
    static bool attr_set = false;
    if (!attr_set) {
        cudaFuncSetAttribute(sinkhorn_kernel,
                             cudaFuncAttributeMaxDynamicSharedMemorySize, shbytes);
        attr_set = true;
    }
    sinkhorn_kernel<<<B, 1024, shbytes>>>(s, nrows, out);
}

// round 9
// speedup vs baseline: 1.3272x; 1.3272x over previous
#include <cuda_runtime.h>
#include <cuda_fp16.h>

#define EPS 1e-4f
#define NDIM 512
#define NH2 256              // half2 per row
#define CHUNKS 8
#define CROWS 64             // rows per chunk
#define BMAX 128

__device__ __half2 g_H[(size_t)BMAX * NDIM * NH2];       // 64 MB fp16 copy
__device__ float   g_part[2][BMAX][CHUNKS][NDIM];        // ping-pong col partials
__device__ float   g_rsum[2][BMAX][CHUNKS];              // ping-pong r-sum partials

__device__ __forceinline__ float4 z4f() { return make_float4(0.f, 0.f, 0.f, 0.f); }
__device__ __forceinline__ float2 h2f(unsigned u) {
    __half2 h = *reinterpret_cast<__half2*>(&u);
    return __half22float2(h);
}
__device__ __forceinline__ float2 pack_h4(float4 v) {
    __half2 h0 = __floats2half2_rn(v.x, v.y);
    __half2 h1 = __floats2half2_rn(v.z, v.w);
    float2 r;
    r.x = __uint_as_float(*reinterpret_cast<unsigned*>(&h0));
    r.y = __uint_as_float(*reinterpret_cast<unsigned*>(&h1));
    return r;
}
// dot of a 512-col fp16 row slice: u0 = cols 8L..8L+7, u1 = cols 256+8L..+7
__device__ __forceinline__ float dot_row(uint4 u0, uint4 u1,
                                         float4 c0, float4 c1,
                                         float4 c2, float4 c3) {
    float2 f0 = h2f(u0.x), f1 = h2f(u0.y), f2 = h2f(u0.z), f3 = h2f(u0.w);
    float2 f4 = h2f(u1.x), f5 = h2f(u1.y), f6 = h2f(u1.z), f7 = h2f(u1.w);
    float d0 = 0.f, d1 = 0.f, d2 = 0.f, d3 = 0.f;
    d0 = fmaf(f0.x, c0.x, d0); d1 = fmaf(f0.y, c0.y, d1);
    d2 = fmaf(f0.x * 0.f + f1.x, c0.z, d2); d3 = fmaf(f1.y, c0.w, d3);
    d0 = fmaf(f2.x, c1.x, d0); d1 = fmaf(f2.y, c1.y, d1);
    d2 = fmaf(f3.x, c1.z, d2); d3 = fmaf(f3.y, c1.w, d3);
    d0 = fmaf(f4.x, c2.x, d0); d1 = fmaf(f4.y, c2.y, d1);
    d2 = fmaf(f5.x, c2.z, d2); d3 = fmaf(f5.y, c2.w, d3);
    d0 = fmaf(f6.x, c3.x, d0); d1 = fmaf(f6.y, c3.y, d1);
    d2 = fmaf(f7.x, c3.z, d2); d3 = fmaf(f7.y, c3.w, d3);
    return (d0 + d1) + (d2 + d3);
}

// prologue: finish the pending column step from partials in buffer `sel`.
// writes c_sh[512] (0 outside block) and returns EPS * sum(c).
__device__ __forceinline__ float finish_col(int sel, int b, int n,
                                            float* c_sh, float* sm8) {
    const int tid = threadIdx.x, lane = tid & 31, w = tid >> 5;
    float sum_r = 0.f;
    #pragma unroll
    for (int k = 0; k < CHUNKS; ++k) sum_r += g_rsum[sel][b][k];
    float part = 0.f;
    #pragma unroll
    for (int rep = 0; rep < 2; ++rep) {
        const int j = tid + rep * 256;
        float t = 0.f;
        #pragma unroll
        for (int k = 0; k < CHUNKS; ++k) t += g_part[sel][b][k][j];
        float cv = (j < n) ? 1.0f / (t + EPS * sum_r) : 0.0f;
        c_sh[j] = cv;
        part += cv;
    }
    #pragma unroll
    for (int o = 16; o; o >>= 1) part += __shfl_xor_sync(0xffffffffu, part, o);
    if (lane == 0) sm8[w] = part;
    __syncthreads();
    float sc = 0.f;
    #pragma unroll
    for (int k = 0; k < 8; ++k) sc += sm8[k];
    return EPS * sc;
}

// ===== kernel A: read fp32 S, build fp16 copy, column partials for iter 0 =====
__global__ __launch_bounds__(256, 4)
void k_pass0(const float* __restrict__ s, const int* __restrict__ nrows) {
    __shared__ __align__(16) float sm[8 * NDIM];
    const int b = blockIdx.y, chunk = blockIdx.x;
    const int tid = threadIdx.x, lane = tid & 31, w = tid >> 5;
    const int n = nrows[b];
    const float* __restrict__ S = s + (size_t)b * NDIM * NDIM;
    __half2* __restrict__ H = g_H + (size_t)b * NDIM * NH2;

    float4 a0 = z4f(), a1 = z4f(), a2 = z4f(), a3 = z4f();
    const int row0 = chunk * CROWS + w * 8;
    #pragma unroll 1
    for (int k = 0; k < 8; ++k) {
        const int i = row0 + k;
        if (i >= n) break;
        const float4* __restrict__ row = (const float4*)(S + (size_t)i * NDIM);
        float4 v0 = __ldcs(row + lane);
        float4 v1 = __ldcs(row + lane + 32);
        float4 v2 = __ldcs(row + lane + 64);
        float4 v3 = __ldcs(row + lane + 96);
        a0.x += v0.x; a0.y += v0.y; a0.z += v0.z; a0.w += v0.w;
        a1.x += v1.x; a1.y += v1.y; a1.z += v1.z; a1.w += v1.w;
        a2.x += v2.x; a2.y += v2.y; a2.z += v2.z; a2.w += v2.w;
        a3.x += v3.x; a3.y += v3.y; a3.z += v3.z; a3.w += v3.w;
        float2* __restrict__ Hrow = (float2*)(H + (size_t)i * NH2);
        Hrow[lane]      = pack_h4(v0);
        Hrow[lane + 32] = pack_h4(v1);
        Hrow[lane + 64] = pack_h4(v2);
        Hrow[lane + 96] = pack_h4(v3);
    }
    float* smw = sm + w * NDIM;     // lane owns cols 4L.., 128+4L.., 256+4L.., 384+4L..
    *(float4*)(smw + 4 * lane)       = a0;
    *(float4*)(smw + 128 + 4 * lane) = a1;
    *(float4*)(smw + 256 + 4 * lane) = a2;
    *(float4*)(smw + 384 + 4 * lane) = a3;
    __syncthreads();
    #pragma unroll
    for (int rep = 0; rep < 2; ++rep) {
        const int j = tid + rep * 256;
        float t = 0.f;
        #pragma unroll
        for (int ww = 0; ww < 8; ++ww) t += sm[ww * NDIM + j];
        g_part[0][b][chunk][j] = t;
    }
    if (tid == 0) {
        int act = n - chunk * CROWS;
        act = act < 0 ? 0 : (act > CROWS ? CROWS : act);
        g_rsum[0][b][chunk] = (float)act;   // r = 1 on active rows
    }
}

// ===== kernel C: finish col step (buf sel) + row step + new col partials ======
__global__ __launch_bounds__(256, 4)
void k_fused(const int* __restrict__ nrows, int sel) {
    __shared__ __align__(16) float sm[8 * NDIM];
    __shared__ __align__(16) float c_sh[NDIM];
    __shared__ float sm8[8];
    const int b = blockIdx.y, chunk = blockIdx.x;
    const int tid = threadIdx.x, lane = tid & 31, w = tid >> 5;
    const int n = nrows[b];
    const __half2* __restrict__ H = g_H + (size_t)b * NDIM * NH2;

    const float eps_c = finish_col(sel, b, n, c_sh, sm8);
    __syncthreads();

    const float4* __restrict__ c4s = (const float4*)c_sh;
    const float4 c0 = c4s[2 * lane],      c1 = c4s[2 * lane + 1];
    const float4 c2 = c4s[64 + 2 * lane], c3 = c4s[64 + 2 * lane + 1];
    float4 a0 = z4f(), a1 = z4f(), a2 = z4f(), a3 = z4f();
    float rpart = 0.f;
    const int row0 = chunk * CROWS + w * 8;
    #pragma unroll 1
    for (int k = 0; k < 8; ++k) {
        const int i = row0 + k;
        if (i >= n) break;
        const uint4* __restrict__ rowH = (const uint4*)(H + (size_t)i * NH2);
        uint4 u0 = rowH[lane];
        uint4 u1 = rowH[lane + 32];
        float t = dot_row(u0, u1, c0, c1, c2, c3);
        #pragma unroll
        for (int o = 16; o; o >>= 1) t += __shfl_xor_sync(0xffffffffu, t, o);
        const float ri = 1.0f / (t + eps_c);
        rpart += ri;
        float2 f0 = h2f(u0.x), f1 = h2f(u0.y), f2 = h2f(u0.z), f3 = h2f(u0.w);
        float2 f4 = h2f(u1.x), f5 = h2f(u1.y), f6 = h2f(u1.z), f7 = h2f(u1.w);
        a0.x = fmaf(ri, f0.x, a0.x); a0.y = fmaf(ri, f0.y, a0.y);
        a0.z = fmaf(ri, f1.x, a0.z); a0.w = fmaf(ri, f1.y, a0.w);
        a1.x = fmaf(ri, f2.x, a1.x); a1.y = fmaf(ri, f2.y, a1.y);
        a1.z = fmaf(ri, f3.x, a1.z); a1.w = fmaf(ri, f3.y, a1.w);
        a2.x = fmaf(ri, f4.x, a2.x); a2.y = fmaf(ri, f4.y, a2.y);
        a2.z = fmaf(ri, f5.x, a2.z); a2.w = fmaf(ri, f5.y, a2.w);
        a3.x = fmaf(ri, f6.x, a3.x); a3.y = fmaf(ri, f6.y, a3.y);
        a3.z = fmaf(ri, f7.x, a3.z); a3.w = fmaf(ri, f7.y, a3.w);
    }
    float* smw = sm + w * NDIM;     // lane owns cols 8L..8L+7 and 256+8L..+7
    *(float4*)(smw + 8 * lane)           = a0;
    *(float4*)(smw + 8 * lane + 4)       = a1;
    *(float4*)(smw + 256 + 8 * lane)     = a2;
    *(float4*)(smw + 256 + 8 * lane + 4) = a3;
    if (lane == 0) sm8[w] = rpart;       // rpart warp-uniform
    __syncthreads();
    const int dst = sel ^ 1;
    #pragma unroll
    for (int rep = 0; rep < 2; ++rep) {
        const int j = tid + rep * 256;
        float t = 0.f;
        #pragma unroll
        for (int ww = 0; ww < 8; ++ww) t += sm[ww * NDIM + j];
        g_part[dst][b][chunk][j] = t;
    }
    if (tid == 0) {
        float rs = 0.f;
        #pragma unroll
        for (int k = 0; k < 8; ++k) rs += sm8[k];
        g_rsum[dst][b][chunk] = rs;
    }
}

// ===== kernel D: finish col step (buf 0) + final row step + write output ======
__global__ __launch_bounds__(256, 4)
void k_final(const int* __restrict__ nrows, float* __restrict__ out) {
    __shared__ __align__(16) float c_sh[NDIM];
    __shared__ float sm8[8];
    const int b = blockIdx.y, chunk = blockIdx.x;
    const int tid = threadIdx.x, lane = tid & 31, w = tid >> 5;
    const int n = nrows[b];
    const __half2* __restrict__ H = g_H + (size_t)b * NDIM * NH2;
    float* __restrict__ O = out + (size_t)b * NDIM * NDIM;

    const float eps_c = finish_col(0, b, n, c_sh, sm8);

    const float4* __restrict__ c4s = (const float4*)c_sh;
    const float4 c0 = c4s[2 * lane],      c1 = c4s[2 * lane + 1];
    const float4 c2 = c4s[64 + 2 * lane], c3 = c4s[64 + 2 * lane + 1];
    const int row0 = chunk * CROWS + w * 8;
    #pragma unroll 1
    for (int k = 0; k < 8; ++k) {
        const int i = row0 + k;
        float4* __restrict__ orow = (float4*)(O + (size_t)i * NDIM);
        if (i < n) {
            const uint4* __restrict__ rowH = (const uint4*)(H + (size_t)i * NH2);
            uint4 u0 = rowH[lane];
            uint4 u1 = rowH[lane + 32];
            float t = dot_row(u0, u1, c0, c1, c2, c3);
            #pragma unroll
            for (int o = 16; o; o >>= 1) t += __shfl_xor_sync(0xffffffffu, t, o);
            const float ri = 1.0f / (t + eps_c);
            float2 f0 = h2f(u0.x), f1 = h2f(u0.y), f2 = h2f(u0.z), f3 = h2f(u0.w);
            float2 f4 = h2f(u1.x), f5 = h2f(u1.y), f6 = h2f(u1.z), f7 = h2f(u1.w);
            float4 v;
            v.x = (f0.x + EPS) * ri * c0.x; v.y = (f0.y + EPS) * ri * c0.y;
            v.z = (f1.x + EPS) * ri * c0.z; v.w = (f1.y + EPS) * ri * c0.w;
            __stcs(orow + 2 * lane, v);
            v.x = (f2.x + EPS) * ri * c1.x; v.y = (f2.y + EPS) * ri * c1.y;
            v.z = (f3.x + EPS) * ri * c1.z; v.w = (f3.y + EPS) * ri * c1.w;
            __stcs(orow + 2 * lane + 1, v);
            v.x = (f4.x + EPS) * ri * c2.x; v.y = (f4.y + EPS) * ri * c2.y;
            v.z = (f5.x + EPS) * ri * c2.z; v.w = (f5.y + EPS) * ri * c2.w;
            __stcs(orow + 64 + 2 * lane, v);
            v.x = (f6.x + EPS) * ri * c3.x; v.y = (f6.y + EPS) * ri * c3.y;
            v.z = (f7.x + EPS) * ri * c3.z; v.w = (f7.y + EPS) * ri * c3.w;
            __stcs(orow + 64 + 2 * lane + 1, v);
        } else {
            const float4 z = z4f();
            __stcs(orow + 2 * lane, z);
            __stcs(orow + 2 * lane + 1, z);
            __stcs(orow + 64 + 2 * lane, z);
            __stcs(orow + 64 + 2 * lane + 1, z);
        }
    }
}

extern "C" void kernel_launch(void* const* d_in, const int* in_sizes, int n_in,
                              void* d_out, int out_size) {
    const float* s     = (const float*)d_in[0];
    const int*   nrows = (const int*)d_in[1];
    float*       out   = (float*)d_out;
    const int B = in_sizes[1];
    dim3 grid(CHUNKS, B);
    k_pass0<<<grid, 256>>>(s, nrows);        // iter 0 (col) partials -> buf0
    k_fused<<<grid, 256>>>(nrows, 0);        // iters 1,2 -> buf1
    k_fused<<<grid, 256>>>(nrows, 1);        // iters 3,4 -> buf0
    k_fused<<<grid, 256>>>(nrows, 0);        // iters 5,6 -> buf1
    k_fused<<<grid, 256>>>(nrows, 1);        // iters 7,8 -> buf0
    k_final<<<grid, 256>>>(nrows, out);      // iter 9 (row) + write
}

// round 10
// speedup vs baseline: 1.5254x; 1.1493x over previous
#include <cuda_runtime.h>
#include <cuda_fp16.h>

#define EPS 1e-4f
#define NDIM 512
#define H2S 131072   // half2 per sample

__device__ __half2 g_half[128 * (size_t)H2S];   // 64 MB fp16 working copy

__device__ __forceinline__ float4 z4f() { return make_float4(0.f, 0.f, 0.f, 0.f); }
__device__ __forceinline__ float2 h2f(unsigned u) {
    __half2 h = *reinterpret_cast<__half2*>(&u);
    return __half22float2(h);
}
__device__ __forceinline__ float2 pack_h4(float4 v) {
    __half2 h0 = __floats2half2_rn(v.x, v.y);
    __half2 h1 = __floats2half2_rn(v.z, v.w);
    float2 r;
    r.x = __uint_as_float(*reinterpret_cast<unsigned*>(&h0));
    r.y = __uint_as_float(*reinterpret_cast<unsigned*>(&h1));
    return r;
}

__global__ __launch_bounds__(1024, 1)
void sinkhorn_kernel(const float* __restrict__ s,
                     const int* __restrict__ nrows,
                     float* __restrict__ out) {
    extern __shared__ __align__(16) float red[];        // 32*512 floats = 64 KB
    __shared__ __align__(16) float c_sh[NDIM];
    __shared__ float ssumA[32];
    __shared__ float ssumB[32];

    const int b    = blockIdx.x;
    const int tid  = threadIdx.x;
    const int lane = tid & 31;
    const int wid  = tid >> 5;
    const int n    = nrows[b];
    const bool g2  = (n > 256);
    const float* __restrict__ S = s   + (size_t)b * (NDIM * NDIM);
    float* __restrict__       O = out + (size_t)b * (NDIM * NDIM);
    __half2* __restrict__     H = g_half + (size_t)b * H2S;
    const float4* __restrict__ c4s = (const float4*)c_sh;

    // ========== pass 0: column sums (r = 1) + fp16 conversion of active rows ====
    {
        const int j4    = (tid & 127) << 2;
        const int slice = tid >> 7;                      // 0..7
        const int jh    = j4 >> 1;                       // half2 col index
        float4 a0 = z4f(), a1 = z4f(), a2 = z4f(), a3 = z4f();
        if (j4 < n) {
            int i = slice;
            for (; i + 24 < n; i += 32) {
                float4 v0 = *(const float4*)(S + (size_t)(i)      * NDIM + j4);
                float4 v1 = *(const float4*)(S + (size_t)(i + 8)  * NDIM + j4);
                float4 v2 = *(const float4*)(S + (size_t)(i + 16) * NDIM + j4);
                float4 v3 = *(const float4*)(S + (size_t)(i + 24) * NDIM + j4);
                a0.x += v0.x; a0.y += v0.y; a0.z += v0.z; a0.w += v0.w;
                a1.x += v1.x; a1.y += v1.y; a1.z += v1.z; a1.w += v1.w;
                a2.x += v2.x; a2.y += v2.y; a2.z += v2.z; a2.w += v2.w;
                a3.x += v3.x; a3.y += v3.y; a3.z += v3.z; a3.w += v3.w;
                *(float2*)(H + (size_t)(i)      * (NDIM/2) + jh) = pack_h4(v0);
                *(float2*)(H + (size_t)(i + 8)  * (NDIM/2) + jh) = pack_h4(v1);
                *(float2*)(H + (size_t)(i + 16) * (NDIM/2) + jh) = pack_h4(v2);
                *(float2*)(H + (size_t)(i + 24) * (NDIM/2) + jh) = pack_h4(v3);
            }
            for (; i < n; i += 8) {
                float4 v0 = *(const float4*)(S + (size_t)i * NDIM + j4);
                a0.x += v0.x; a0.y += v0.y; a0.z += v0.z; a0.w += v0.w;
                *(float2*)(H + (size_t)i * (NDIM/2) + jh) = pack_h4(v0);
            }
            a0.x += a1.x + a2.x + a3.x; a0.y += a1.y + a2.y + a3.y;
            a0.z += a1.z + a2.z + a3.z; a0.w += a1.w + a2.w + a3.w;
        }
        *(float4*)(red + slice * NDIM + j4) = a0;
        __syncthreads();

        float cv = 0.0f;
        if (tid < n) {
            float cs = 0.0f;
            #pragma unroll
            for (int ss = 0; ss < 8; ++ss) cs += red[ss * NDIM + tid];
            cv = 1.0f / (cs + EPS * (float)n);
        }
        if (tid < NDIM) c_sh[tid] = cv;
        float v = cv;
        #pragma unroll
        for (int o = 16; o; o >>= 1) v += __shfl_xor_sync(0xffffffffu, v, o);
        if (lane == 0) ssumB[wid] = v;
        __syncthreads();
    }
    float sum_c = 0.0f;
    #pragma unroll
    for (int k = 0; k < 32; ++k) sum_c += ssumB[k];

    // ==== 4 fused passes: row(2f+1) + col(2f+2), one-row software pipeline ======
    #pragma unroll 1
    for (int f = 0; f < 4; ++f) {
        const float eps_c = EPS * sum_c;
        float4 acc0 = z4f(), acc1 = z4f(), acc2 = z4f(), acc3 = z4f();
        float rpart = 0.0f;
        const uint4 uz = make_uint4(0u, 0u, 0u, 0u);

        int i = wid;
        uint4 u0 = uz, u1 = uz;
        if (i < n) {
            const uint4* __restrict__ rowH = (const uint4*)(H + (size_t)i * (NDIM/2));
            u0 = rowH[lane];
            if (g2) u1 = rowH[lane + 32];
        }
        #pragma unroll 1
        while (i < n) {
            const int inx = i + 32;
            uint4 n0 = uz, n1 = uz;
            if (inx < n) {                               // prefetch next row first
                const uint4* __restrict__ rowN = (const uint4*)(H + (size_t)inx * (NDIM/2));
                n0 = rowN[lane];
                if (g2) n1 = rowN[lane + 32];
            }

            // dot with c from SMEM (c regs are transient)
            float t;
            {
                float4 c0 = c4s[lane * 2],      c1 = c4s[lane * 2 + 1];
                float4 c2 = c4s[64 + lane * 2], c3 = c4s[64 + lane * 2 + 1];
                float2 f0 = h2f(u0.x), f1 = h2f(u0.y), f2 = h2f(u0.z), f3 = h2f(u0.w);
                float2 f4 = h2f(u1.x), f5 = h2f(u1.y), f6 = h2f(u1.z), f7 = h2f(u1.w);
                float d0 = 0.f, d1 = 0.f, d2 = 0.f, d3 = 0.f;
                d0 = fmaf(f0.x, c0.x, d0); d1 = fmaf(f0.y, c0.y, d1);
                d2 = fmaf(f1.x, c0.z, d2); d3 = fmaf(f1.y, c0.w, d3);
                d0 = fmaf(f2.x, c1.x, d0); d1 = fmaf(f2.y, c1.y, d1);
                d2 = fmaf(f3.x, c1.z, d2); d3 = fmaf(f3.y, c1.w, d3);
                d0 = fmaf(f4.x, c2.x, d0); d1 = fmaf(f4.y, c2.y, d1);
                d2 = fmaf(f5.x, c2.z, d2); d3 = fmaf(f5.y, c2.w, d3);
                d0 = fmaf(f6.x, c3.x, d0); d1 = fmaf(f6.y, c3.y, d1);
                d2 = fmaf(f7.x, c3.z, d2); d3 = fmaf(f7.y, c3.w, d3);
                t = (d0 + d1) + (d2 + d3);
            }
            #pragma unroll
            for (int o = 16; o; o >>= 1) t += __shfl_xor_sync(0xffffffffu, t, o);
            const float ri = 1.0f / (t + eps_c);
            rpart += ri;

            {   // re-convert (cheap F2F) and accumulate column partials
                float2 f0 = h2f(u0.x), f1 = h2f(u0.y), f2 = h2f(u0.z), f3 = h2f(u0.w);
                acc0.x = fmaf(ri, f0.x, acc0.x); acc0.y = fmaf(ri, f0.y, acc0.y);
                acc0.z = fmaf(ri, f1.x, acc0.z); acc0.w = fmaf(ri, f1.y, acc0.w);
                acc1.x = fmaf(ri, f2.x, acc1.x); acc1.y = fmaf(ri, f2.y, acc1.y);
                acc1.z = fmaf(ri, f3.x, acc1.z); acc1.w = fmaf(ri, f3.y, acc1.w);
            }
            {
                float2 f4 = h2f(u1.x), f5 = h2f(u1.y), f6 = h2f(u1.z), f7 = h2f(u1.w);
                acc2.x = fmaf(ri, f4.x, acc2.x); acc2.y = fmaf(ri, f4.y, acc2.y);
                acc2.z = fmaf(ri, f5.x, acc2.z); acc2.w = fmaf(ri, f5.y, acc2.w);
                acc3.x = fmaf(ri, f6.x, acc3.x); acc3.y = fmaf(ri, f6.y, acc3.y);
                acc3.z = fmaf(ri, f7.x, acc3.z); acc3.w = fmaf(ri, f7.y, acc3.w);
            }
            u0 = n0; u1 = n1; i = inx;
        }

        float4* __restrict__ rw = (float4*)(red + wid * NDIM);
        rw[lane * 2]          = acc0;
        rw[lane * 2 + 1]      = acc1;
        rw[64 + lane * 2]     = acc2;
        rw[64 + lane * 2 + 1] = acc3;
        if (lane == 0) ssumA[wid] = rpart;   // warp-uniform
        __syncthreads();

        float sum_r = 0.0f;
        #pragma unroll
        for (int k = 0; k < 32; ++k) sum_r += ssumA[k];

        float cv = 0.0f;
        if (tid < n) {
            float cs = 0.0f;
            #pragma unroll
            for (int w = 0; w < 32; ++w) cs += red[w * NDIM + tid];
            cv = 1.0f / (cs + EPS * sum_r);
        }
        if (tid < NDIM) c_sh[tid] = cv;
        float v = cv;
        #pragma unroll
        for (int o = 16; o; o >>= 1) v += __shfl_xor_sync(0xffffffffu, v, o);
        if (lane == 0) ssumB[wid] = v;
        __syncthreads();
        sum_c = 0.0f;
        #pragma unroll
        for (int k = 0; k < 32; ++k) sum_c += ssumB[k];
    }

    // ========== final pass: row step (iter 9) on fp32 S, fused output write =====
    {
        const float eps_c = EPS * sum_c;
        const bool g3 = (n > 384);
        for (int i = wid; i < n; i += 32) {
            const float4* __restrict__ row = (const float4*)(S + (size_t)i * NDIM);
            float4* __restrict__ orow = (float4*)(O + (size_t)i * NDIM);
            float4 v0 = __ldcs(row + lane);
            float4 v1 = __ldcs(row + lane + 32);
            float4 v2 = z4f(), v3 = z4f();
            if (g2) v2 = __ldcs(row + lane + 64);
            if (g3) v3 = __ldcs(row + lane + 96);
            float4 c0 = c4s[lane], c1 = c4s[lane + 32];
            float4 c2 = c4s[lane + 64], c3 = c4s[lane + 96];

            float d0 = 0.f, d1 = 0.f, d2 = 0.f, d3 = 0.f;
            d0 = fmaf(v0.x, c0.x, d0); d1 = fmaf(v0.y, c0.y, d1);
            d2 = fmaf(v0.z, c0.z, d2); d3 = fmaf(v0.w, c0.w, d3);
            d0 = fmaf(v1.x, c1.x, d0); d1 = fmaf(v1.y, c1.y, d1);
            d2 = fmaf(v1.z, c1.z, d2); d3 = fmaf(v1.w, c1.w, d3);
            d0 = fmaf(v2.x, c2.x, d0); d1 = fmaf(v2.y, c2.y, d1);
            d2 = fmaf(v2.z, c2.z, d2); d3 = fmaf(v2.w, c2.w, d3);
            d0 = fmaf(v3.x, c3.x, d0); d1 = fmaf(v3.y, c3.y, d1);
            d2 = fmaf(v3.z, c3.z, d2); d3 = fmaf(v3.w, c3.w, d3);
            float t = (d0 + d1) + (d2 + d3);
            #pragma unroll
            for (int o = 16; o; o >>= 1) t += __shfl_xor_sync(0xffffffffu, t, o);
            const float ri = 1.0f / (t + eps_c);

            float4 w;
            w.x = (v0.x + EPS) * ri * c0.x; w.y = (v0.y + EPS) * ri * c0.y;
            w.z = (v0.z + EPS) * ri * c0.z; w.w = (v0.w + EPS) * ri * c0.w;
            __stcs(orow + lane, w);
            w.x = (v1.x + EPS) * ri * c1.x; w.y = (v1.y + EPS) * ri * c1.y;
            w.z = (v1.z + EPS) * ri * c1.z; w.w = (v1.w + EPS) * ri * c1.w;
            __stcs(orow + lane + 32, w);
            w.x = (v2.x + EPS) * ri * c2.x; w.y = (v2.y + EPS) * ri * c2.y;
            w.z = (v2.z + EPS) * ri * c2.z; w.w = (v2.w + EPS) * ri * c2.w;
            __stcs(orow + lane + 64, w);
            w.x = (v3.x + EPS) * ri * c3.x; w.y = (v3.y + EPS) * ri * c3.y;
            w.z = (v3.z + EPS) * ri * c3.z; w.w = (v3.w + EPS) * ri * c3.w;
            __stcs(orow + lane + 96, w);
        }
        // zero-fill rows i >= n
        float4* __restrict__ O4 = (float4*)O;
        const float4 z = z4f();
        for (int idx = n * 128 + tid; idx < NDIM * 128; idx += 1024)
            __stcs(O4 + idx, z);
    }
}

extern "C" void kernel_launch(void* const* d_in, const int* in_sizes, int n_in,
                              void* d_out, int out_size) {
    const float* s     = (const float*)d_in[0];
    const int*   nrows = (const int*)d_in[1];
    float*       out   = (float*)d_out;
    const int B = in_sizes[1];
    const int shbytes = 32 * NDIM * sizeof(float);   // 64 KB dynamic
    static bool attr_set = false;
    if (!attr_set) {
        cudaFuncSetAttribute(sinkhorn_kernel,
                             cudaFuncAttributeMaxDynamicSharedMemorySize, shbytes);
        attr_set = true;
    }
    sinkhorn_kernel<<<B, 1024, shbytes>>>(s, nrows, out);
}

// round 11
// speedup vs baseline: 1.5409x; 1.0101x over previous
#include <cuda_runtime.h>
#include <cuda_fp16.h>

#define EPS 1e-4f
#define NDIM 512
#define H2S 131072   // half2 per sample

__device__ __half2 g_half[128 * (size_t)H2S];   // 64 MB fp16 working copy

__device__ __forceinline__ float4 z4f() { return make_float4(0.f, 0.f, 0.f, 0.f); }
__device__ __forceinline__ float2 h2f(unsigned u) {
    __half2 h = *reinterpret_cast<__half2*>(&u);
    return __half22float2(h);
}
__device__ __forceinline__ float2 pack_h4(float4 v) {
    __half2 h0 = __floats2half2_rn(v.x, v.y);
    __half2 h1 = __floats2half2_rn(v.z, v.w);
    float2 r;
    r.x = __uint_as_float(*reinterpret_cast<unsigned*>(&h0));
    r.y = __uint_as_float(*reinterpret_cast<unsigned*>(&h1));
    return r;
}

__global__ __launch_bounds__(1024, 1)
void sinkhorn_kernel(const float* __restrict__ s,
                     const int* __restrict__ nrows,
                     float* __restrict__ out) {
    extern __shared__ __align__(16) float red[];        // 32*512 floats = 64 KB
    __shared__ __align__(16) float c_sh[NDIM];
    __shared__ float ssumA[32];
    __shared__ float ssumB[32];

    const int b    = blockIdx.x;
    const int tid  = threadIdx.x;
    const int lane = tid & 31;
    const int wid  = tid >> 5;
    const int n    = nrows[b];
    const bool g2  = (n > 256);
    const float* __restrict__ S = s   + (size_t)b * (NDIM * NDIM);
    float* __restrict__       O = out + (size_t)b * (NDIM * NDIM);
    __half2* __restrict__     H = g_half + (size_t)b * H2S;
    const float4* __restrict__ c4s = (const float4*)c_sh;

    // ========== pass 0: column sums (r = 1) + fp16 conversion of active rows ====
    // S is read exactly once in the whole kernel -> __ldcs (evict-first) so the
    // fp16 working copy H stays L2-resident for all later passes.
    {
        const int j4    = (tid & 127) << 2;
        const int slice = tid >> 7;                      // 0..7
        const int jh    = j4 >> 1;                       // half2 col index
        float4 a0 = z4f(), a1 = z4f(), a2 = z4f(), a3 = z4f();
        if (j4 < n) {
            int i = slice;
            for (; i + 24 < n; i += 32) {
                float4 v0 = __ldcs((const float4*)(S + (size_t)(i)      * NDIM + j4));
                float4 v1 = __ldcs((const float4*)(S + (size_t)(i + 8)  * NDIM + j4));
                float4 v2 = __ldcs((const float4*)(S + (size_t)(i + 16) * NDIM + j4));
                float4 v3 = __ldcs((const float4*)(S + (size_t)(i + 24) * NDIM + j4));
                a0.x += v0.x; a0.y += v0.y; a0.z += v0.z; a0.w += v0.w;
                a1.x += v1.x; a1.y += v1.y; a1.z += v1.z; a1.w += v1.w;
                a2.x += v2.x; a2.y += v2.y; a2.z += v2.z; a2.w += v2.w;
                a3.x += v3.x; a3.y += v3.y; a3.z += v3.z; a3.w += v3.w;
                *(float2*)(H + (size_t)(i)      * (NDIM/2) + jh) = pack_h4(v0);
                *(float2*)(H + (size_t)(i + 8)  * (NDIM/2) + jh) = pack_h4(v1);
                *(float2*)(H + (size_t)(i + 16) * (NDIM/2) + jh) = pack_h4(v2);
                *(float2*)(H + (size_t)(i + 24) * (NDIM/2) + jh) = pack_h4(v3);
            }
            for (; i < n; i += 8) {
                float4 v0 = __ldcs((const float4*)(S + (size_t)i * NDIM + j4));
                a0.x += v0.x; a0.y += v0.y; a0.z += v0.z; a0.w += v0.w;
                *(float2*)(H + (size_t)i * (NDIM/2) + jh) = pack_h4(v0);
            }
            a0.x += a1.x + a2.x + a3.x; a0.y += a1.y + a2.y + a3.y;
            a0.z += a1.z + a2.z + a3.z; a0.w += a1.w + a2.w + a3.w;
        }
        *(float4*)(red + slice * NDIM + j4) = a0;
        __syncthreads();

        float cv = 0.0f;
        if (tid < n) {
            float cs = 0.0f;
            #pragma unroll
            for (int ss = 0; ss < 8; ++ss) cs += red[ss * NDIM + tid];
            cv = 1.0f / (cs + EPS * (float)n);
        }
        if (tid < NDIM) c_sh[tid] = cv;
        float v = cv;
        #pragma unroll
        for (int o = 16; o; o >>= 1) v += __shfl_xor_sync(0xffffffffu, v, o);
        if (lane == 0) ssumB[wid] = v;
        __syncthreads();
    }
    float sum_c = 0.0f;
    #pragma unroll
    for (int k = 0; k < 32; ++k) sum_c += ssumB[k];

    // ==== 4 fused passes: row(2f+1) + col(2f+2), one-row software pipeline ======
    #pragma unroll 1
    for (int f = 0; f < 4; ++f) {
        const float eps_c = EPS * sum_c;
        float4 acc0 = z4f(), acc1 = z4f(), acc2 = z4f(), acc3 = z4f();
        float rpart = 0.0f;
        const uint4 uz = make_uint4(0u, 0u, 0u, 0u);

        int i = wid;
        uint4 u0 = uz, u1 = uz;
        if (i < n) {
            const uint4* __restrict__ rowH = (const uint4*)(H + (size_t)i * (NDIM/2));
            u0 = rowH[lane];
            if (g2) u1 = rowH[lane + 32];
        }
        #pragma unroll 1
        while (i < n) {
            const int inx = i + 32;
            uint4 n0 = uz, n1 = uz;
            if (inx < n) {                               // prefetch next row first
                const uint4* __restrict__ rowN = (const uint4*)(H + (size_t)inx * (NDIM/2));
                n0 = rowN[lane];
                if (g2) n1 = rowN[lane + 32];
            }

            // dot with c from SMEM (c regs are transient)
            float t;
            {
                float4 c0 = c4s[lane * 2],      c1 = c4s[lane * 2 + 1];
                float4 c2 = c4s[64 + lane * 2], c3 = c4s[64 + lane * 2 + 1];
                float2 f0 = h2f(u0.x), f1 = h2f(u0.y), f2 = h2f(u0.z), f3 = h2f(u0.w);
                float2 f4 = h2f(u1.x), f5 = h2f(u1.y), f6 = h2f(u1.z), f7 = h2f(u1.w);
                float d0 = 0.f, d1 = 0.f, d2 = 0.f, d3 = 0.f;
                d0 = fmaf(f0.x, c0.x, d0); d1 = fmaf(f0.y, c0.y, d1);
                d2 = fmaf(f1.x, c0.z, d2); d3 = fmaf(f1.y, c0.w, d3);
                d0 = fmaf(f2.x, c1.x, d0); d1 = fmaf(f2.y, c1.y, d1);
                d2 = fmaf(f3.x, c1.z, d2); d3 = fmaf(f3.y, c1.w, d3);
                d0 = fmaf(f4.x, c2.x, d0); d1 = fmaf(f4.y, c2.y, d1);
                d2 = fmaf(f5.x, c2.z, d2); d3 = fmaf(f5.y, c2.w, d3);
                d0 = fmaf(f6.x, c3.x, d0); d1 = fmaf(f6.y, c3.y, d1);
                d2 = fmaf(f7.x, c3.z, d2); d3 = fmaf(f7.y, c3.w, d3);
                t = (d0 + d1) + (d2 + d3);
            }
            #pragma unroll
            for (int o = 16; o; o >>= 1) t += __shfl_xor_sync(0xffffffffu, t, o);
            const float ri = 1.0f / (t + eps_c);
            rpart += ri;

            {   // re-convert (cheap F2F) and accumulate column partials
                float2 f0 = h2f(u0.x), f1 = h2f(u0.y), f2 = h2f(u0.z), f3 = h2f(u0.w);
                acc0.x = fmaf(ri, f0.x, acc0.x); acc0.y = fmaf(ri, f0.y, acc0.y);
                acc0.z = fmaf(ri, f1.x, acc0.z); acc0.w = fmaf(ri, f1.y, acc0.w);
                acc1.x = fmaf(ri, f2.x, acc1.x); acc1.y = fmaf(ri, f2.y, acc1.y);
                acc1.z = fmaf(ri, f3.x, acc1.z); acc1.w = fmaf(ri, f3.y, acc1.w);
            }
            {
                float2 f4 = h2f(u1.x), f5 = h2f(u1.y), f6 = h2f(u1.z), f7 = h2f(u1.w);
                acc2.x = fmaf(ri, f4.x, acc2.x); acc2.y = fmaf(ri, f4.y, acc2.y);
                acc2.z = fmaf(ri, f5.x, acc2.z); acc2.w = fmaf(ri, f5.y, acc2.w);
                acc3.x = fmaf(ri, f6.x, acc3.x); acc3.y = fmaf(ri, f6.y, acc3.y);
                acc3.z = fmaf(ri, f7.x, acc3.z); acc3.w = fmaf(ri, f7.y, acc3.w);
            }
            u0 = n0; u1 = n1; i = inx;
        }

        float4* __restrict__ rw = (float4*)(red + wid * NDIM);
        rw[lane * 2]          = acc0;
        rw[lane * 2 + 1]      = acc1;
        rw[64 + lane * 2]     = acc2;
        rw[64 + lane * 2 + 1] = acc3;
        if (lane == 0) ssumA[wid] = rpart;   // warp-uniform
        __syncthreads();

        float sum_r = 0.0f;
        #pragma unroll
        for (int k = 0; k < 32; ++k) sum_r += ssumA[k];

        float cv = 0.0f;
        if (tid < n) {
            float cs = 0.0f;
            #pragma unroll
            for (int w = 0; w < 32; ++w) cs += red[w * NDIM + tid];
            cv = 1.0f / (cs + EPS * sum_r);
        }
        if (tid < NDIM) c_sh[tid] = cv;
        float v = cv;
        #pragma unroll
        for (int o = 16; o; o >>= 1) v += __shfl_xor_sync(0xffffffffu, v, o);
        if (lane == 0) ssumB[wid] = v;
        __syncthreads();
        sum_c = 0.0f;
        #pragma unroll
        for (int k = 0; k < 32; ++k) sum_c += ssumB[k];
    }

    // ====== final pass: row step (iter 9) on the fp16 copy, fused output write ==
    {
        const float eps_c = EPS * sum_c;
        const uint4 uz = make_uint4(0u, 0u, 0u, 0u);
        for (int i = wid; i < n; i += 32) {
            const uint4* __restrict__ rowH = (const uint4*)(H + (size_t)i * (NDIM/2));
            float4* __restrict__ orow = (float4*)(O + (size_t)i * NDIM);
            uint4 u0 = __ldcs(rowH + lane);
            uint4 u1 = uz;
            if (g2) u1 = __ldcs(rowH + lane + 32);

            float4 c0 = c4s[lane * 2],      c1 = c4s[lane * 2 + 1];
            float4 c2 = c4s[64 + lane * 2], c3 = c4s[64 + lane * 2 + 1];

            float2 f0 = h2f(u0.x), f1 = h2f(u0.y), f2 = h2f(u0.z), f3 = h2f(u0.w);
            float2 f4 = h2f(u1.x), f5 = h2f(u1.y), f6 = h2f(u1.z), f7 = h2f(u1.w);
            float d0 = 0.f, d1 = 0.f, d2 = 0.f, d3 = 0.f;
            d0 = fmaf(f0.x, c0.x, d0); d1 = fmaf(f0.y, c0.y, d1);
            d2 = fmaf(f1.x, c0.z, d2); d3 = fmaf(f1.y, c0.w, d3);
            d0 = fmaf(f2.x, c1.x, d0); d1 = fmaf(f2.y, c1.y, d1);
            d2 = fmaf(f3.x, c1.z, d2); d3 = fmaf(f3.y, c1.w, d3);
            d0 = fmaf(f4.x, c2.x, d0); d1 = fmaf(f4.y, c2.y, d1);
            d2 = fmaf(f5.x, c2.z, d2); d3 = fmaf(f5.y, c2.w, d3);
            d0 = fmaf(f6.x, c3.x, d0); d1 = fmaf(f6.y, c3.y, d1);
            d2 = fmaf(f7.x, c3.z, d2); d3 = fmaf(f7.y, c3.w, d3);
            float t = (d0 + d1) + (d2 + d3);
            #pragma unroll
            for (int o = 16; o; o >>= 1) t += __shfl_xor_sync(0xffffffffu, t, o);
            const float ri = 1.0f / (t + eps_c);

            float4 w;
            w.x = (f0.x + EPS) * ri * c0.x; w.y = (f0.y + EPS) * ri * c0.y;
            w.z = (f1.x + EPS) * ri * c0.z; w.w = (f1.y + EPS) * ri * c0.w;
            __stcs(orow + lane * 2, w);
            w.x = (f2.x + EPS) * ri * c1.x; w.y = (f2.y + EPS) * ri * c1.y;
            w.z = (f3.x + EPS) * ri * c1.z; w.w = (f3.y + EPS) * ri * c1.w;
            __stcs(orow + lane * 2 + 1, w);
            w.x = (f4.x + EPS) * ri * c2.x; w.y = (f4.y + EPS) * ri * c2.y;
            w.z = (f5.x + EPS) * ri * c2.z; w.w = (f5.y + EPS) * ri * c2.w;
            __stcs(orow + 64 + lane * 2, w);
            w.x = (f6.x + EPS) * ri * c3.x; w.y = (f6.y + EPS) * ri * c3.y;
            w.z = (f7.x + EPS) * ri * c3.z; w.w = (f7.y + EPS) * ri * c3.w;
            __stcs(orow + 64 + lane * 2 + 1, w);
        }
        // zero-fill rows i >= n
        float4* __restrict__ O4 = (float4*)O;
        const float4 z = z4f();
        for (int idx = n * 128 + tid; idx < NDIM * 128; idx += 1024)
            __stcs(O4 + idx, z);
    }
}

extern "C" void kernel_launch(void* const* d_in, const int* in_sizes, int n_in,
                              void* d_out, int out_size) {
    const float* s     = (const float*)d_in[0];
    const int*   nrows = (const int*)d_in[1];
    float*       out   = (float*)d_out;
    const int B = in_sizes[1];
    const int shbytes = 32 * NDIM * sizeof(float);   // 64 KB dynamic
    static bool attr_set = false;
    if (!attr_set) {
        cudaFuncSetAttribute(sinkhorn_kernel,
                             cudaFuncAttributeMaxDynamicSharedMemorySize, shbytes);
        attr_set = true;
    }
    sinkhorn_kernel<<<B, 1024, shbytes>>>(s, nrows, out);
}